// round 8
// baseline (speedup 1.0000x reference)
#include <cuda_runtime.h>
#include <cstdint>

// ---------------------------------------------------------------------------
// SimpleSNN: B=4096, D_in=784, H=800, D_out=10, T=32
// Exactness invariant: every per-output accumulation chain keeps the exact
// sequential k/h order of the reference (fma with s in {0,1} is bit-exact).
// No predicated accumulation (pred-as-guard = 13cy, killed R6).
// ---------------------------------------------------------------------------

#define B_     4096
#define DIN    784
#define H_     800
#define DOUT   10
#define TSTEPS 32
#define NW     25
#define NROWS  (TSTEPS * B_)       // 131072 (t,i) rows

__device__ unsigned g_xbits[B_ * NW];
__device__ float    g_cur1[B_ * H_];
__device__ unsigned g_spk[NW * NROWS];        // [w][row], row = t*B_ + i
__device__ float    g_cur2[NROWS * DOUT];

typedef unsigned long long ull;

// ------------------------------- helpers -----------------------------------
__device__ __forceinline__ ull pack2(float lo, float hi) {
    ull d;
    asm("mov.b64 %0, {%1, %2};" : "=l"(d) : "f"(lo), "f"(hi));
    return d;
}
__device__ __forceinline__ void unpack2(ull v, float &lo, float &hi) {
    asm("mov.b64 {%0, %1}, %2;" : "=f"(lo), "=f"(hi) : "l"(v));
}
__device__ __forceinline__ ull fma2(ull a, ull b, ull c) {
    ull d;
    asm("fma.rn.f32x2 %0, %1, %2, %3;" : "=l"(d) : "l"(a), "l"(b), "l"(c));
    return d;
}

// ------------------------------- threefry ----------------------------------
#define ROTL32(x, d) (((x) << (d)) | ((x) >> (32 - (d))))

__device__ __forceinline__ unsigned threefry_xor(unsigned f) {
    const unsigned k0 = 0u, k1 = 42u;
    const unsigned k2 = 0x1BD11BDAu ^ k0 ^ k1;
    unsigned x0 = 0u + k0;
    unsigned x1 = f + k1;
#define TF_R(r) { x0 += x1; x1 = ROTL32(x1, r); x1 ^= x0; }
    TF_R(13) TF_R(15) TF_R(26) TF_R(6)   x0 += k1; x1 += k2 + 1u;
    TF_R(17) TF_R(29) TF_R(16) TF_R(24)  x0 += k2; x1 += k0 + 2u;
    TF_R(13) TF_R(15) TF_R(26) TF_R(6)   x0 += k0; x1 += k1 + 3u;
    TF_R(17) TF_R(29) TF_R(16) TF_R(24)  x0 += k1; x1 += k2 + 4u;
    TF_R(13) TF_R(15) TF_R(26) TF_R(6)   x0 += k2; x1 += k0 + 5u;
#undef TF_R
    return x0 ^ x1;
}

// K1: Bernoulli encode. One thread per (row, word).
__global__ void __launch_bounds__(256) k_encode(const float *__restrict__ x) {
    int idx = blockIdx.x * 256 + threadIdx.x;
    int i = idx / NW;
    int w = idx % NW;
    int nbits = (w == NW - 1) ? 16 : 32;
    long base = (long)i * DIN + w * 32;
    unsigned word = 0;
    for (int k = 0; k < nbits; k++) {
        long f = base + k;
        unsigned bits = threefry_xor((unsigned)f);
        float u = __uint_as_float((bits >> 9) | 0x3f800000u) - 1.0f;
        if (u < x[f]) word |= (1u << k);
    }
    g_xbits[idx] = word;
}

// K2: cur1 = xbits @ W1^T + b1.  BM=256 x BN=32, 256 threads, TM=4 TN=8.
// f32x2 lanes = ROW PAIRS (lane-lo row 2p, lane-hi row 2p+1); weights stored
// as dup pairs in smem. Per-output chain: ascending j in one lane (exact).
__global__ void __launch_bounds__(256) k_gemm1(const float *__restrict__ W1,
                                               const float *__restrict__ b1) {
    __shared__ unsigned Aw[256];
    __shared__ __align__(16) ull Bs2[32][34];     // [jj][c] dup pairs; stride 34
    int tid = threadIdx.x;
    int rowbase = blockIdx.x * 256;
    int colbase = blockIdx.y * 32;
    int tc = tid & 3, tr = tid >> 2;              // 4 col-groups x 64 row-groups
    int c0 = tc * 8, r0 = tr * 4;

    ull acc[2][8];                                // [row-pair][col]
#pragma unroll
    for (int p = 0; p < 2; p++)
#pragma unroll
        for (int q = 0; q < 8; q++) acc[p][q] = 0ull;

    for (int kw = 0; kw < NW; kw++) {
        Aw[tid] = g_xbits[(rowbase + tid) * NW + kw];
        {
            int c = tid >> 3;                     // 0..31
            int jv = (tid & 7) * 4;               // 0,4,..28
            int j = kw * 32 + jv;
            float4 bv = make_float4(0.f, 0.f, 0.f, 0.f);
            if (j < DIN)
                bv = *(const float4 *)(W1 + (long)(colbase + c) * DIN + j);
            Bs2[jv + 0][c] = pack2(bv.x, bv.x);
            Bs2[jv + 1][c] = pack2(bv.y, bv.y);
            Bs2[jv + 2][c] = pack2(bv.z, bv.z);
            Bs2[jv + 3][c] = pack2(bv.w, bv.w);
        }
        __syncthreads();

        unsigned a[4];
#pragma unroll
        for (int r = 0; r < 4; r++) a[r] = Aw[r0 + r];

#pragma unroll
        for (int jj = 0; jj < 32; jj++) {
            ulonglong2 d01 = *(const ulonglong2 *)&Bs2[jj][c0];
            ulonglong2 d23 = *(const ulonglong2 *)&Bs2[jj][c0 + 2];
            ulonglong2 d45 = *(const ulonglong2 *)&Bs2[jj][c0 + 4];
            ulonglong2 d67 = *(const ulonglong2 *)&Bs2[jj][c0 + 6];
#pragma unroll
            for (int p = 0; p < 2; p++) {
                float sl = (a[2 * p]     & (1u << jj)) ? 1.0f : 0.0f;
                float sh = (a[2 * p + 1] & (1u << jj)) ? 1.0f : 0.0f;
                ull m = pack2(sl, sh);
                acc[p][0] = fma2(m, d01.x, acc[p][0]);
                acc[p][1] = fma2(m, d01.y, acc[p][1]);
                acc[p][2] = fma2(m, d23.x, acc[p][2]);
                acc[p][3] = fma2(m, d23.y, acc[p][3]);
                acc[p][4] = fma2(m, d45.x, acc[p][4]);
                acc[p][5] = fma2(m, d45.y, acc[p][5]);
                acc[p][6] = fma2(m, d67.x, acc[p][6]);
                acc[p][7] = fma2(m, d67.y, acc[p][7]);
            }
        }
        __syncthreads();
    }

    float bb[8];
#pragma unroll
    for (int q = 0; q < 8; q++) bb[q] = b1[colbase + c0 + q];
#pragma unroll
    for (int p = 0; p < 2; p++) {
        float lo[8], hi[8];
#pragma unroll
        for (int q = 0; q < 8; q++) unpack2(acc[p][q], lo[q], hi[q]);
        int rowL = rowbase + r0 + 2 * p;
        int rowH = rowL + 1;
        *(float4 *)(g_cur1 + (long)rowL * H_ + colbase + c0) =
            make_float4(lo[0] + bb[0], lo[1] + bb[1], lo[2] + bb[2], lo[3] + bb[3]);
        *(float4 *)(g_cur1 + (long)rowL * H_ + colbase + c0 + 4) =
            make_float4(lo[4] + bb[4], lo[5] + bb[5], lo[6] + bb[6], lo[7] + bb[7]);
        *(float4 *)(g_cur1 + (long)rowH * H_ + colbase + c0) =
            make_float4(hi[0] + bb[0], hi[1] + bb[1], hi[2] + bb[2], hi[3] + bb[3]);
        *(float4 *)(g_cur1 + (long)rowH * H_ + colbase + c0 + 4) =
            make_float4(hi[4] + bb[4], hi[5] + bb[5], hi[6] + bb[6], hi[7] + bb[7]);
    }
}

// K3: layer-1 IF dynamics -> packed spike raster [w][t*B_+i]. One warp/(row,word).
__global__ void __launch_bounds__(256) k_spikegen() {
    int gtid = blockIdx.x * 256 + threadIdx.x;
    int wid  = gtid >> 5;
    int lane = gtid & 31;
    int i = wid / NW;
    int w = wid % NW;
    float c = g_cur1[(long)i * H_ + w * 32 + lane];
    float v = 0.0f;
#pragma unroll
    for (int t = 0; t < TSTEPS; t++) {
        float h1 = v + c;
        bool s = (h1 >= 1.0f);
        unsigned m = __ballot_sync(0xffffffffu, s);
        if (lane == 0) g_spk[(long)w * NROWS + t * B_ + i] = m;
        v = s ? 0.0f : h1;
    }
}

// K4: cur2 = spk1 @ W2^T + b2. TWO rows per thread (65536 threads) so the
// shared weight LDS amortizes; f32x2 lanes = output pairs, dup spike mult.
__global__ void __launch_bounds__(256) k_gemm2(const float *__restrict__ W2,
                                               const float *__restrict__ b2) {
    __shared__ __align__(16) ull W2p[H_ * 5];     // 4000 ull = 32000B
    for (int idx = threadIdx.x; idx < H_ * 5; idx += 256) {
        int h  = idx / 5;
        int op = idx % 5;
        W2p[idx] = pack2(W2[(2 * op) * H_ + h], W2[(2 * op + 1) * H_ + h]);
    }
    __syncthreads();

    int gid = blockIdx.x * 256 + threadIdx.x;     // 0 .. 65535
    int rowA = gid;
    int rowB = gid + 65536;

    ull accA[5], accB[5];
#pragma unroll
    for (int o = 0; o < 5; o++) { accA[o] = 0ull; accB[o] = 0ull; }

    for (int w = 0; w < NW; w++) {
        unsigned wdA = g_spk[(long)w * NROWS + rowA];   // coalesced
        unsigned wdB = g_spk[(long)w * NROWS + rowB];
        const ull *bp = &W2p[w * 160];
#pragma unroll
        for (int k2 = 0; k2 < 16; k2++) {
            const ull *p = bp + k2 * 10;
            ulonglong2 q0 = *(const ulonglong2 *)(p + 0);
            ulonglong2 q1 = *(const ulonglong2 *)(p + 2);
            ulonglong2 q2 = *(const ulonglong2 *)(p + 4);
            ulonglong2 q3 = *(const ulonglong2 *)(p + 6);
            ulonglong2 q4 = *(const ulonglong2 *)(p + 8);
            // k = 2*k2 : weight pairs q0.x q0.y q1.x q1.y q2.x
            {
                float sA = (wdA & (1u << (2 * k2))) ? 1.0f : 0.0f;
                ull mA = pack2(sA, sA);
                accA[0] = fma2(mA, q0.x, accA[0]);
                accA[1] = fma2(mA, q0.y, accA[1]);
                accA[2] = fma2(mA, q1.x, accA[2]);
                accA[3] = fma2(mA, q1.y, accA[3]);
                accA[4] = fma2(mA, q2.x, accA[4]);
                float sB = (wdB & (1u << (2 * k2))) ? 1.0f : 0.0f;
                ull mB = pack2(sB, sB);
                accB[0] = fma2(mB, q0.x, accB[0]);
                accB[1] = fma2(mB, q0.y, accB[1]);
                accB[2] = fma2(mB, q1.x, accB[2]);
                accB[3] = fma2(mB, q1.y, accB[3]);
                accB[4] = fma2(mB, q2.x, accB[4]);
            }
            // k = 2*k2+1 : weight pairs q2.y q3.x q3.y q4.x q4.y
            {
                float sA = (wdA & (1u << (2 * k2 + 1))) ? 1.0f : 0.0f;
                ull mA = pack2(sA, sA);
                accA[0] = fma2(mA, q2.y, accA[0]);
                accA[1] = fma2(mA, q3.x, accA[1]);
                accA[2] = fma2(mA, q3.y, accA[2]);
                accA[3] = fma2(mA, q4.x, accA[3]);
                accA[4] = fma2(mA, q4.y, accA[4]);
                float sB = (wdB & (1u << (2 * k2 + 1))) ? 1.0f : 0.0f;
                ull mB = pack2(sB, sB);
                accB[0] = fma2(mB, q2.y, accB[0]);
                accB[1] = fma2(mB, q3.x, accB[1]);
                accB[2] = fma2(mB, q3.y, accB[2]);
                accB[3] = fma2(mB, q4.x, accB[3]);
                accB[4] = fma2(mB, q4.y, accB[4]);
            }
        }
    }

    float lo, hi;
    ull *outA = (ull *)(g_cur2 + (long)rowA * DOUT);
    ull *outB = (ull *)(g_cur2 + (long)rowB * DOUT);
#pragma unroll
    for (int o = 0; o < 5; o++) {
        float blo = b2[2 * o], bhi = b2[2 * o + 1];
        unpack2(accA[o], lo, hi); outA[o] = pack2(lo + blo, hi + bhi);
        unpack2(accB[o], lo, hi); outB[o] = pack2(lo + blo, hi + bhi);
    }
}

// K5: layer-2 IF scan -> spike counts. One thread per (i, o).
__global__ void __launch_bounds__(256) k_scan(float *__restrict__ out) {
    int id = blockIdx.x * 256 + threadIdx.x;
    int i = id / DOUT;
    int o = id % DOUT;
    float v = 0.0f, cnt = 0.0f;
#pragma unroll
    for (int t = 0; t < TSTEPS; t++) {
        float c2 = g_cur2[((long)t * B_ + i) * DOUT + o];
        float h2 = v + c2;
        bool s = (h2 >= 1.0f);
        cnt += s ? 1.0f : 0.0f;
        v = s ? 0.0f : h2;
    }
    out[id] = cnt;
}

// ---------------------------------------------------------------------------
extern "C" void kernel_launch(void *const *d_in, const int *in_sizes, int n_in,
                              void *d_out, int out_size) {
    const float *x  = (const float *)d_in[0];
    const float *W1 = (const float *)d_in[1];
    const float *b1 = (const float *)d_in[2];
    const float *W2 = (const float *)d_in[3];
    const float *b2 = (const float *)d_in[4];
    float *out = (float *)d_out;

    k_encode<<<400, 256>>>(x);

    k_gemm1<<<dim3(16, 25), 256>>>(W1, b1);

    k_spikegen<<<12800, 256>>>();

    k_gemm2<<<256, 256>>>(W2, b2);

    k_scan<<<160, 256>>>(out);
}

// round 9
// speedup vs baseline: 1.9406x; 1.9406x over previous
#include <cuda_runtime.h>
#include <cstdint>

// ---------------------------------------------------------------------------
// SimpleSNN: B=4096, D_in=784, H=800, D_out=10, T=32
// Exactness invariant: every per-output accumulation chain keeps the exact
// sequential k/h order of the reference (fma with s in {0,1} is bit-exact).
// Known pathologies (measured): predicated accumulation (R6, pred-as-guard
// 13cy) and row-pair-lane gemm1 with dup-weight smem (R8) each ~3x gemm1.
// Best-known gemm1 = R7 form; best-known gemm2 = R8 form (2 rows/thread).
// ---------------------------------------------------------------------------

#define B_     4096
#define DIN    784
#define H_     800
#define DOUT   10
#define TSTEPS 32
#define NW     25
#define NROWS  (TSTEPS * B_)       // 131072 (t,i) rows

__device__ unsigned g_xbits[B_ * NW];
__device__ float    g_cur1[B_ * H_];
__device__ unsigned g_spk[NW * NROWS];        // [w][row], row = t*B_ + i
__device__ float    g_cur2[NROWS * DOUT];

typedef unsigned long long ull;

// ------------------------------- helpers -----------------------------------
__device__ __forceinline__ ull pack2(float lo, float hi) {
    ull d;
    asm("mov.b64 %0, {%1, %2};" : "=l"(d) : "f"(lo), "f"(hi));
    return d;
}
__device__ __forceinline__ void unpack2(ull v, float &lo, float &hi) {
    asm("mov.b64 {%0, %1}, %2;" : "=f"(lo), "=f"(hi) : "l"(v));
}
__device__ __forceinline__ ull fma2(ull a, ull b, ull c) {
    ull d;
    asm("fma.rn.f32x2 %0, %1, %2, %3;" : "=l"(d) : "l"(a), "l"(b), "l"(c));
    return d;
}

// ------------------------------- threefry ----------------------------------
#define ROTL32(x, d) (((x) << (d)) | ((x) >> (32 - (d))))

__device__ __forceinline__ unsigned threefry_xor(unsigned f) {
    const unsigned k0 = 0u, k1 = 42u;
    const unsigned k2 = 0x1BD11BDAu ^ k0 ^ k1;
    unsigned x0 = 0u + k0;
    unsigned x1 = f + k1;
#define TF_R(r) { x0 += x1; x1 = ROTL32(x1, r); x1 ^= x0; }
    TF_R(13) TF_R(15) TF_R(26) TF_R(6)   x0 += k1; x1 += k2 + 1u;
    TF_R(17) TF_R(29) TF_R(16) TF_R(24)  x0 += k2; x1 += k0 + 2u;
    TF_R(13) TF_R(15) TF_R(26) TF_R(6)   x0 += k0; x1 += k1 + 3u;
    TF_R(17) TF_R(29) TF_R(16) TF_R(24)  x0 += k1; x1 += k2 + 4u;
    TF_R(13) TF_R(15) TF_R(26) TF_R(6)   x0 += k2; x1 += k0 + 5u;
#undef TF_R
    return x0 ^ x1;
}

// K1: Bernoulli encode. One thread per (row, word).
__global__ void __launch_bounds__(256) k_encode(const float *__restrict__ x) {
    int idx = blockIdx.x * 256 + threadIdx.x;
    int i = idx / NW;
    int w = idx % NW;
    int nbits = (w == NW - 1) ? 16 : 32;
    long base = (long)i * DIN + w * 32;
    unsigned word = 0;
    for (int k = 0; k < nbits; k++) {
        long f = base + k;
        unsigned bits = threefry_xor((unsigned)f);
        float u = __uint_as_float((bits >> 9) | 0x3f800000u) - 1.0f;
        if (u < x[f]) word |= (1u << k);
    }
    g_xbits[idx] = word;
}

// K2: cur1 = xbits @ W1^T + b1.  BM=256 x BN=32, 256 threads, TM=4 TN=8.
// (R7 form — best known.) Per-output chain: ascending j, FFMA2 dup multiplier.
__global__ void __launch_bounds__(256) k_gemm1(const float *__restrict__ W1,
                                               const float *__restrict__ b1) {
    __shared__ unsigned Aw[256];
    __shared__ __align__(16) float Bs[32][36];    // 36*4=144B rows, 16B aligned
    int tid = threadIdx.x;
    int rowbase = blockIdx.x * 256;
    int colbase = blockIdx.y * 32;
    int tc = tid & 3, tr = tid >> 2;              // 4 col-groups x 64 row-groups
    int c0 = tc * 8, r0 = tr * 4;

    ull acc[4][4];
#pragma unroll
    for (int r = 0; r < 4; r++)
#pragma unroll
        for (int q = 0; q < 4; q++) acc[r][q] = 0ull;

    for (int kw = 0; kw < NW; kw++) {
        Aw[tid] = g_xbits[(rowbase + tid) * NW + kw];
        {
            int c = tid >> 3;                     // 0..31
            int jv = (tid & 7) * 4;               // 0,4,..28
            int j = kw * 32 + jv;
            float4 bv = make_float4(0.f, 0.f, 0.f, 0.f);
            if (j < DIN)
                bv = *(const float4 *)(W1 + (long)(colbase + c) * DIN + j);
            Bs[jv + 0][c] = bv.x;
            Bs[jv + 1][c] = bv.y;
            Bs[jv + 2][c] = bv.z;
            Bs[jv + 3][c] = bv.w;
        }
        __syncthreads();

        unsigned a[4];
#pragma unroll
        for (int r = 0; r < 4; r++) a[r] = Aw[r0 + r];

#pragma unroll
        for (int jj = 0; jj < 32; jj++) {
            ulonglong2 p0 = *(const ulonglong2 *)&Bs[jj][c0];       // c0..c0+3
            ulonglong2 p1 = *(const ulonglong2 *)&Bs[jj][c0 + 4];   // c0+4..c0+7
#pragma unroll
            for (int r = 0; r < 4; r++) {
                float s = (a[r] & (1u << jj)) ? 1.0f : 0.0f;
                ull ss = pack2(s, s);
                acc[r][0] = fma2(ss, p0.x, acc[r][0]);
                acc[r][1] = fma2(ss, p0.y, acc[r][1]);
                acc[r][2] = fma2(ss, p1.x, acc[r][2]);
                acc[r][3] = fma2(ss, p1.y, acc[r][3]);
            }
        }
        __syncthreads();
    }

    float bb[8];
#pragma unroll
    for (int q = 0; q < 8; q++) bb[q] = b1[colbase + c0 + q];
#pragma unroll
    for (int r = 0; r < 4; r++) {
        int row = rowbase + r0 + r;
        float o0, o1, o2, o3, o4, o5, o6, o7;
        unpack2(acc[r][0], o0, o1);
        unpack2(acc[r][1], o2, o3);
        unpack2(acc[r][2], o4, o5);
        unpack2(acc[r][3], o6, o7);
        float4 lo = make_float4(o0 + bb[0], o1 + bb[1], o2 + bb[2], o3 + bb[3]);
        float4 hi = make_float4(o4 + bb[4], o5 + bb[5], o6 + bb[6], o7 + bb[7]);
        *(float4 *)(g_cur1 + (long)row * H_ + colbase + c0)     = lo;
        *(float4 *)(g_cur1 + (long)row * H_ + colbase + c0 + 4) = hi;
    }
}

// K3: layer-1 IF dynamics -> packed spike raster [w][t*B_+i]. One warp/(row,word).
// Each lane keeps the ballot for t==lane, then ONE store instruction (32 sectors).
__global__ void __launch_bounds__(256) k_spikegen() {
    int gtid = blockIdx.x * 256 + threadIdx.x;
    int wid  = gtid >> 5;
    int lane = gtid & 31;
    int i = wid / NW;
    int w = wid % NW;
    float c = g_cur1[(long)i * H_ + w * 32 + lane];
    float v = 0.0f;
    unsigned msave = 0;
#pragma unroll
    for (int t = 0; t < TSTEPS; t++) {
        float h1 = v + c;
        bool s = (h1 >= 1.0f);
        unsigned m = __ballot_sync(0xffffffffu, s);
        if (t == lane) msave = m;
        v = s ? 0.0f : h1;
    }
    g_spk[(long)w * NROWS + lane * B_ + i] = msave;
}

// K4: cur2 = spk1 @ W2^T + b2. TWO rows per thread (65536 threads); weight LDS
// amortized over both rows; f32x2 lanes = output pairs, dup spike multiplier.
// (R8 form — measured 64.4us.)
__global__ void __launch_bounds__(256) k_gemm2(const float *__restrict__ W2,
                                               const float *__restrict__ b2) {
    __shared__ __align__(16) ull W2p[H_ * 5];     // 4000 ull = 32000B
    for (int idx = threadIdx.x; idx < H_ * 5; idx += 256) {
        int h  = idx / 5;
        int op = idx % 5;
        W2p[idx] = pack2(W2[(2 * op) * H_ + h], W2[(2 * op + 1) * H_ + h]);
    }
    __syncthreads();

    int gid = blockIdx.x * 256 + threadIdx.x;     // 0 .. 65535
    int rowA = gid;
    int rowB = gid + 65536;

    ull accA[5], accB[5];
#pragma unroll
    for (int o = 0; o < 5; o++) { accA[o] = 0ull; accB[o] = 0ull; }

    for (int w = 0; w < NW; w++) {
        unsigned wdA = g_spk[(long)w * NROWS + rowA];   // coalesced
        unsigned wdB = g_spk[(long)w * NROWS + rowB];
        const ull *bp = &W2p[w * 160];
#pragma unroll
        for (int k2 = 0; k2 < 16; k2++) {
            const ull *p = bp + k2 * 10;
            ulonglong2 q0 = *(const ulonglong2 *)(p + 0);
            ulonglong2 q1 = *(const ulonglong2 *)(p + 2);
            ulonglong2 q2 = *(const ulonglong2 *)(p + 4);
            ulonglong2 q3 = *(const ulonglong2 *)(p + 6);
            ulonglong2 q4 = *(const ulonglong2 *)(p + 8);
            {
                float sA = (wdA & (1u << (2 * k2))) ? 1.0f : 0.0f;
                ull mA = pack2(sA, sA);
                accA[0] = fma2(mA, q0.x, accA[0]);
                accA[1] = fma2(mA, q0.y, accA[1]);
                accA[2] = fma2(mA, q1.x, accA[2]);
                accA[3] = fma2(mA, q1.y, accA[3]);
                accA[4] = fma2(mA, q2.x, accA[4]);
                float sB = (wdB & (1u << (2 * k2))) ? 1.0f : 0.0f;
                ull mB = pack2(sB, sB);
                accB[0] = fma2(mB, q0.x, accB[0]);
                accB[1] = fma2(mB, q0.y, accB[1]);
                accB[2] = fma2(mB, q1.x, accB[2]);
                accB[3] = fma2(mB, q1.y, accB[3]);
                accB[4] = fma2(mB, q2.x, accB[4]);
            }
            {
                float sA = (wdA & (1u << (2 * k2 + 1))) ? 1.0f : 0.0f;
                ull mA = pack2(sA, sA);
                accA[0] = fma2(mA, q2.y, accA[0]);
                accA[1] = fma2(mA, q3.x, accA[1]);
                accA[2] = fma2(mA, q3.y, accA[2]);
                accA[3] = fma2(mA, q4.x, accA[3]);
                accA[4] = fma2(mA, q4.y, accA[4]);
                float sB = (wdB & (1u << (2 * k2 + 1))) ? 1.0f : 0.0f;
                ull mB = pack2(sB, sB);
                accB[0] = fma2(mB, q2.y, accB[0]);
                accB[1] = fma2(mB, q3.x, accB[1]);
                accB[2] = fma2(mB, q3.y, accB[2]);
                accB[3] = fma2(mB, q4.x, accB[3]);
                accB[4] = fma2(mB, q4.y, accB[4]);
            }
        }
    }

    float lo, hi;
    ull *outA = (ull *)(g_cur2 + (long)rowA * DOUT);
    ull *outB = (ull *)(g_cur2 + (long)rowB * DOUT);
#pragma unroll
    for (int o = 0; o < 5; o++) {
        float blo = b2[2 * o], bhi = b2[2 * o + 1];
        unpack2(accA[o], lo, hi); outA[o] = pack2(lo + blo, hi + bhi);
        unpack2(accB[o], lo, hi); outB[o] = pack2(lo + blo, hi + bhi);
    }
}

// K5: layer-2 IF scan -> spike counts. One thread per (i, o).
__global__ void __launch_bounds__(256) k_scan(float *__restrict__ out) {
    int id = blockIdx.x * 256 + threadIdx.x;
    int i = id / DOUT;
    int o = id % DOUT;
    float v = 0.0f, cnt = 0.0f;
#pragma unroll
    for (int t = 0; t < TSTEPS; t++) {
        float c2 = g_cur2[((long)t * B_ + i) * DOUT + o];
        float h2 = v + c2;
        bool s = (h2 >= 1.0f);
        cnt += s ? 1.0f : 0.0f;
        v = s ? 0.0f : h2;
    }
    out[id] = cnt;
}

// ---------------------------------------------------------------------------
extern "C" void kernel_launch(void *const *d_in, const int *in_sizes, int n_in,
                              void *d_out, int out_size) {
    const float *x  = (const float *)d_in[0];
    const float *W1 = (const float *)d_in[1];
    const float *b1 = (const float *)d_in[2];
    const float *W2 = (const float *)d_in[3];
    const float *b2 = (const float *)d_in[4];
    float *out = (float *)d_out;

    k_encode<<<400, 256>>>(x);

    k_gemm1<<<dim3(16, 25), 256>>>(W1, b1);

    k_spikegen<<<12800, 256>>>();

    k_gemm2<<<256, 256>>>(W2, b2);

    k_scan<<<160, 256>>>(out);
}

// round 10
// speedup vs baseline: 1.9615x; 1.0108x over previous
#include <cuda_runtime.h>
#include <cstdint>

// ---------------------------------------------------------------------------
// SimpleSNN: B=4096, D_in=784, H=800, D_out=10, T=32
// Exactness invariant: every per-output accumulation chain keeps the exact
// sequential k/h order of the reference (fma with s in {0,1} is bit-exact).
// Measured pathologies: predicated accumulation (R6), row-pair-lane gemm1
// with dup-weight smem (R8). gemm1 (R7 form) is AT its rt3-FFMA2 roofline
// (~100us); do not touch. gemm2 floor ~41us; attacking stall slack.
// ---------------------------------------------------------------------------

#define B_     4096
#define DIN    784
#define H_     800
#define DOUT   10
#define TSTEPS 32
#define NW     25
#define NROWS  (TSTEPS * B_)       // 131072 (t,i) rows

__device__ unsigned g_xbits[B_ * NW];
__device__ float    g_cur1[B_ * H_];
__device__ unsigned g_spk[NW * NROWS];        // [w][row], row = t*B_ + i
__device__ float    g_cur2[NROWS * DOUT];

typedef unsigned long long ull;

// ------------------------------- helpers -----------------------------------
__device__ __forceinline__ ull pack2(float lo, float hi) {
    ull d;
    asm("mov.b64 %0, {%1, %2};" : "=l"(d) : "f"(lo), "f"(hi));
    return d;
}
__device__ __forceinline__ void unpack2(ull v, float &lo, float &hi) {
    asm("mov.b64 {%0, %1}, %2;" : "=f"(lo), "=f"(hi) : "l"(v));
}
__device__ __forceinline__ ull fma2(ull a, ull b, ull c) {
    ull d;
    asm("fma.rn.f32x2 %0, %1, %2, %3;" : "=l"(d) : "l"(a), "l"(b), "l"(c));
    return d;
}

// ------------------------------- threefry ----------------------------------
#define ROTL32(x, d) (((x) << (d)) | ((x) >> (32 - (d))))

__device__ __forceinline__ unsigned threefry_xor(unsigned f) {
    const unsigned k0 = 0u, k1 = 42u;
    const unsigned k2 = 0x1BD11BDAu ^ k0 ^ k1;
    unsigned x0 = 0u + k0;
    unsigned x1 = f + k1;
#define TF_R(r) { x0 += x1; x1 = ROTL32(x1, r); x1 ^= x0; }
    TF_R(13) TF_R(15) TF_R(26) TF_R(6)   x0 += k1; x1 += k2 + 1u;
    TF_R(17) TF_R(29) TF_R(16) TF_R(24)  x0 += k2; x1 += k0 + 2u;
    TF_R(13) TF_R(15) TF_R(26) TF_R(6)   x0 += k0; x1 += k1 + 3u;
    TF_R(17) TF_R(29) TF_R(16) TF_R(24)  x0 += k1; x1 += k2 + 4u;
    TF_R(13) TF_R(15) TF_R(26) TF_R(6)   x0 += k2; x1 += k0 + 5u;
#undef TF_R
    return x0 ^ x1;
}

// K1: Bernoulli encode. One thread per (row, word).
__global__ void __launch_bounds__(256) k_encode(const float *__restrict__ x) {
    int idx = blockIdx.x * 256 + threadIdx.x;
    int i = idx / NW;
    int w = idx % NW;
    int nbits = (w == NW - 1) ? 16 : 32;
    long base = (long)i * DIN + w * 32;
    unsigned word = 0;
    for (int k = 0; k < nbits; k++) {
        long f = base + k;
        unsigned bits = threefry_xor((unsigned)f);
        float u = __uint_as_float((bits >> 9) | 0x3f800000u) - 1.0f;
        if (u < x[f]) word |= (1u << k);
    }
    g_xbits[idx] = word;
}

// K2: cur1 = xbits @ W1^T + b1.  BM=256 x BN=32, 256 threads, TM=4 TN=8.
// (R7 form — at rt3 roofline.) Per-output chain: ascending j, FFMA2 dup mult.
__global__ void __launch_bounds__(256) k_gemm1(const float *__restrict__ W1,
                                               const float *__restrict__ b1) {
    __shared__ unsigned Aw[256];
    __shared__ __align__(16) float Bs[32][36];    // 36*4=144B rows, 16B aligned
    int tid = threadIdx.x;
    int rowbase = blockIdx.x * 256;
    int colbase = blockIdx.y * 32;
    int tc = tid & 3, tr = tid >> 2;              // 4 col-groups x 64 row-groups
    int c0 = tc * 8, r0 = tr * 4;

    ull acc[4][4];
#pragma unroll
    for (int r = 0; r < 4; r++)
#pragma unroll
        for (int q = 0; q < 4; q++) acc[r][q] = 0ull;

    for (int kw = 0; kw < NW; kw++) {
        Aw[tid] = g_xbits[(rowbase + tid) * NW + kw];
        {
            int c = tid >> 3;                     // 0..31
            int jv = (tid & 7) * 4;               // 0,4,..28
            int j = kw * 32 + jv;
            float4 bv = make_float4(0.f, 0.f, 0.f, 0.f);
            if (j < DIN)
                bv = *(const float4 *)(W1 + (long)(colbase + c) * DIN + j);
            Bs[jv + 0][c] = bv.x;
            Bs[jv + 1][c] = bv.y;
            Bs[jv + 2][c] = bv.z;
            Bs[jv + 3][c] = bv.w;
        }
        __syncthreads();

        unsigned a[4];
#pragma unroll
        for (int r = 0; r < 4; r++) a[r] = Aw[r0 + r];

#pragma unroll
        for (int jj = 0; jj < 32; jj++) {
            ulonglong2 p0 = *(const ulonglong2 *)&Bs[jj][c0];       // c0..c0+3
            ulonglong2 p1 = *(const ulonglong2 *)&Bs[jj][c0 + 4];   // c0+4..c0+7
#pragma unroll
            for (int r = 0; r < 4; r++) {
                float s = (a[r] & (1u << jj)) ? 1.0f : 0.0f;
                ull ss = pack2(s, s);
                acc[r][0] = fma2(ss, p0.x, acc[r][0]);
                acc[r][1] = fma2(ss, p0.y, acc[r][1]);
                acc[r][2] = fma2(ss, p1.x, acc[r][2]);
                acc[r][3] = fma2(ss, p1.y, acc[r][3]);
            }
        }
        __syncthreads();
    }

    float bb[8];
#pragma unroll
    for (int q = 0; q < 8; q++) bb[q] = b1[colbase + c0 + q];
#pragma unroll
    for (int r = 0; r < 4; r++) {
        int row = rowbase + r0 + r;
        float o0, o1, o2, o3, o4, o5, o6, o7;
        unpack2(acc[r][0], o0, o1);
        unpack2(acc[r][1], o2, o3);
        unpack2(acc[r][2], o4, o5);
        unpack2(acc[r][3], o6, o7);
        float4 lo = make_float4(o0 + bb[0], o1 + bb[1], o2 + bb[2], o3 + bb[3]);
        float4 hi = make_float4(o4 + bb[4], o5 + bb[5], o6 + bb[6], o7 + bb[7]);
        *(float4 *)(g_cur1 + (long)row * H_ + colbase + c0)     = lo;
        *(float4 *)(g_cur1 + (long)row * H_ + colbase + c0 + 4) = hi;
    }
}

// K3: layer-1 IF dynamics -> packed spike raster [w][t*B_+i]. One warp/(row,word).
__global__ void __launch_bounds__(256) k_spikegen() {
    int gtid = blockIdx.x * 256 + threadIdx.x;
    int wid  = gtid >> 5;
    int lane = gtid & 31;
    int i = wid / NW;
    int w = wid % NW;
    float c = g_cur1[(long)i * H_ + w * 32 + lane];
    float v = 0.0f;
    unsigned msave = 0;
#pragma unroll
    for (int t = 0; t < TSTEPS; t++) {
        float h1 = v + c;
        bool s = (h1 >= 1.0f);
        unsigned m = __ballot_sync(0xffffffffu, s);
        if (t == lane) msave = m;
        v = s ? 0.0f : h1;
    }
    g_spk[(long)w * NROWS + lane * B_ + i] = msave;
}

// K4: cur2 = spk1 @ W2^T + b2. TWO rows per thread; software-pipelined:
// ping-pong double buffer on weight-pair loads (LDS->use distance ~30cy) and
// next-w spike prefetch. f32x2 lanes = output pairs; h-ascending chains exact.
__global__ void __launch_bounds__(256) k_gemm2(const float *__restrict__ W2,
                                               const float *__restrict__ b2) {
    __shared__ __align__(16) ull W2p[H_ * 5];     // [h][5 output-pairs] = 32000B
    for (int idx = threadIdx.x; idx < H_ * 5; idx += 256) {
        int h  = idx / 5;
        int op = idx % 5;
        W2p[idx] = pack2(W2[(2 * op) * H_ + h], W2[(2 * op + 1) * H_ + h]);
    }
    __syncthreads();

    int gid = blockIdx.x * 256 + threadIdx.x;     // 0 .. 65535
    int rowA = gid;
    int rowB = gid + 65536;

    ull acc[10];
#pragma unroll
    for (int o = 0; o < 10; o++) acc[o] = 0ull;

    // Prefetch spikes for w=0
    unsigned wdA = g_spk[rowA];
    unsigned wdB = g_spk[rowB];

    for (int w = 0; w < NW; w++) {
        unsigned curA = wdA, curB = wdB;
        // Prefetch next w's spike words (long latency, hidden under 16 blocks)
        int wn = (w + 1 < NW) ? (w + 1) : w;
        wdA = g_spk[(long)wn * NROWS + rowA];
        wdB = g_spk[(long)wn * NROWS + rowB];

        const ull *bp = &W2p[w * 160];

        // process-one-block macro: block j covers k = 2j, 2j+1 with 10 pairs
#define G2_PROC(j, q0, q1, q2, q3, q4)                                        \
        {                                                                     \
            {                                                                 \
                float sA = (curA & (1u << (2 * (j)))) ? 1.0f : 0.0f;          \
                ull mA = pack2(sA, sA);                                       \
                acc[0] = fma2(mA, q0.x, acc[0]);                              \
                acc[1] = fma2(mA, q0.y, acc[1]);                              \
                acc[2] = fma2(mA, q1.x, acc[2]);                              \
                acc[3] = fma2(mA, q1.y, acc[3]);                              \
                acc[4] = fma2(mA, q2.x, acc[4]);                              \
                float sB = (curB & (1u << (2 * (j)))) ? 1.0f : 0.0f;          \
                ull mB = pack2(sB, sB);                                       \
                acc[5] = fma2(mB, q0.x, acc[5]);                              \
                acc[6] = fma2(mB, q0.y, acc[6]);                              \
                acc[7] = fma2(mB, q1.x, acc[7]);                              \
                acc[8] = fma2(mB, q1.y, acc[8]);                              \
                acc[9] = fma2(mB, q2.x, acc[9]);                              \
            }                                                                 \
            {                                                                 \
                float sA = (curA & (1u << (2 * (j) + 1))) ? 1.0f : 0.0f;      \
                ull mA = pack2(sA, sA);                                       \
                acc[0] = fma2(mA, q2.y, acc[0]);                              \
                acc[1] = fma2(mA, q3.x, acc[1]);                              \
                acc[2] = fma2(mA, q3.y, acc[2]);                              \
                acc[3] = fma2(mA, q4.x, acc[3]);                              \
                acc[4] = fma2(mA, q4.y, acc[4]);                              \
                float sB = (curB & (1u << (2 * (j) + 1))) ? 1.0f : 0.0f;      \
                ull mB = pack2(sB, sB);                                       \
                acc[5] = fma2(mB, q2.y, acc[5]);                              \
                acc[6] = fma2(mB, q3.x, acc[6]);                              \
                acc[7] = fma2(mB, q3.y, acc[7]);                              \
                acc[8] = fma2(mB, q4.x, acc[8]);                              \
                acc[9] = fma2(mB, q4.y, acc[9]);                              \
            }                                                                 \
        }

#define G2_LOAD(dst0, dst1, dst2, dst3, dst4, j)                              \
        {                                                                     \
            const ull *p_ = bp + (j) * 10;                                    \
            dst0 = *(const ulonglong2 *)(p_ + 0);                             \
            dst1 = *(const ulonglong2 *)(p_ + 2);                             \
            dst2 = *(const ulonglong2 *)(p_ + 4);                             \
            dst3 = *(const ulonglong2 *)(p_ + 6);                             \
            dst4 = *(const ulonglong2 *)(p_ + 8);                             \
        }

        ulonglong2 a0, a1, a2, a3, a4, c0, c1, c2, c3, c4;
        G2_LOAD(a0, a1, a2, a3, a4, 0)
#pragma unroll
        for (int j = 0; j < 16; j += 2) {
            G2_LOAD(c0, c1, c2, c3, c4, j + 1)
            G2_PROC(j, a0, a1, a2, a3, a4)
            if (j + 2 < 16) G2_LOAD(a0, a1, a2, a3, a4, j + 2)
            G2_PROC(j + 1, c0, c1, c2, c3, c4)
        }
#undef G2_PROC
#undef G2_LOAD
    }

    float lo, hi;
    ull *outA = (ull *)(g_cur2 + (long)rowA * DOUT);
    ull *outB = (ull *)(g_cur2 + (long)rowB * DOUT);
#pragma unroll
    for (int o = 0; o < 5; o++) {
        float blo = b2[2 * o], bhi = b2[2 * o + 1];
        unpack2(acc[o], lo, hi);     outA[o] = pack2(lo + blo, hi + bhi);
        unpack2(acc[o + 5], lo, hi); outB[o] = pack2(lo + blo, hi + bhi);
    }
}

// K5: layer-2 IF scan -> spike counts. One thread per (i, o).
__global__ void __launch_bounds__(256) k_scan(float *__restrict__ out) {
    int id = blockIdx.x * 256 + threadIdx.x;
    int i = id / DOUT;
    int o = id % DOUT;
    float v = 0.0f, cnt = 0.0f;
#pragma unroll
    for (int t = 0; t < TSTEPS; t++) {
        float c2 = g_cur2[((long)t * B_ + i) * DOUT + o];
        float h2 = v + c2;
        bool s = (h2 >= 1.0f);
        cnt += s ? 1.0f : 0.0f;
        v = s ? 0.0f : h2;
    }
    out[id] = cnt;
}

// ---------------------------------------------------------------------------
extern "C" void kernel_launch(void *const *d_in, const int *in_sizes, int n_in,
                              void *d_out, int out_size) {
    const float *x  = (const float *)d_in[0];
    const float *W1 = (const float *)d_in[1];
    const float *b1 = (const float *)d_in[2];
    const float *W2 = (const float *)d_in[3];
    const float *b2 = (const float *)d_in[4];
    float *out = (float *)d_out;

    k_encode<<<400, 256>>>(x);

    k_gemm1<<<dim3(16, 25), 256>>>(W1, b1);

    k_spikegen<<<12800, 256>>>();

    k_gemm2<<<256, 256>>>(W2, b2);

    k_scan<<<160, 256>>>(out);
}